// round 15
// baseline (speedup 1.0000x reference)
#include <cuda_runtime.h>
#include <cuda_fp16.h>

#define Bsz 1024
#define Tst 300
#define NH  256
#define NBG 8      // batch groups (128 rows)
#define NGS 16     // gate-slice CTAs per group (64 gate cols each)
#define NCTA 128

#define BLK_W0XH 0
#define BLK_W0XL 2
#define BLK_W0HH 4
#define BLK_W0HL 20
#define BLK_W1XH 36
#define BLK_W1XL 52
#define BLK_W1HH 68
#define BLK_W1HL 84
#define NBLK     100
#define SMEM_SZ  (NBLK * 2048 + 512)

// -------------------- device scratch --------------------
__device__ unsigned g_Wfrag[(size_t)NGS * NBLK * 512];        // fp16 hi/lo W fragments
__device__ float    g_biasP[2 * NGS * 64];
__device__ unsigned g_Xfrag[(size_t)Tst * NBG * 8 * 2 * 128]; // fp16 A fragments (20 MB)
__device__ unsigned g_Hfrag[2 * 2 * NBG * 8 * 16 * 128];      // fp16 h fragments (2 MB)
__device__ unsigned g_cntA[NBG], g_cntB[NBG];                 // monotonic step counters

__device__ __forceinline__ size_t hoff(int l, int buf, int bg, int mt, int ch) {
    return ((((((size_t)(l * 2 + buf)) * NBG + bg) * 8 + mt) * 16 + ch) * 128);
}
__device__ __forceinline__ size_t xoff(int t, int bg, int mt, int c) {
    return ((((size_t)t * NBG + bg) * 8 + mt) * 2 + c) * 128;
}

__device__ __forceinline__ unsigned pack_h2(float v0, float v1) {
    __half2 h = __floats2half2_rn(v0, v1);
    return *(unsigned*)&h;
}
__device__ __forceinline__ void splitw2(float v0, float v1, unsigned& hi, unsigned& lo) {
    __half h0 = __float2half_rn(v0), h1 = __float2half_rn(v1);
    __half l0 = __float2half_rn(v0 - __half2float(h0));
    __half l1 = __float2half_rn(v1 - __half2float(h1));
    hi = (unsigned)*(unsigned short*)&h0 | ((unsigned)*(unsigned short*)&h1 << 16);
    lo = (unsigned)*(unsigned short*)&l0 | ((unsigned)*(unsigned short*)&l1 << 16);
}
__device__ __forceinline__ float sigm(float x) { return 1.f / (1.f + __expf(-x)); }
__device__ __forceinline__ float tanh_f(float x) {
    x = fminf(fmaxf(x, -15.f), 15.f);
    float e = __expf(2.f * x);
    return __fdividef(e - 1.f, e + 1.f);
}

__device__ __forceinline__ void mma4(float* d, const unsigned* a, unsigned b0, unsigned b1) {
    asm volatile("mma.sync.aligned.m16n8k16.row.col.f32.f16.f16.f32 "
        "{%0,%1,%2,%3}, {%4,%5,%6,%7}, {%8,%9}, {%0,%1,%2,%3};"
        : "+f"(d[0]), "+f"(d[1]), "+f"(d[2]), "+f"(d[3])
        : "r"(a[0]), "r"(a[1]), "r"(a[2]), "r"(a[3]), "r"(b0), "r"(b1));
}

// -------------------- x gather --------------------
__device__ __forceinline__ float fetch_x(const int* __restrict__ input,
                                         const float* __restrict__ emb,
                                         int t, int b, int k) {
    if (k >= 25) return 0.f;
    long flat = (long)t * (Bsz * 25) + b * 25 + k;
    int s = (int)(flat / (Bsz * 300));
    int rr = (int)(flat % (Bsz * 300));
    int bb = rr / 300, e = rr % 300;
    return emb[(long)input[bb * 25 + s] * 300 + e];
}

// -------------------- prep kernels --------------------
__global__ void pack_x_kernel(const int* __restrict__ input, const float* __restrict__ emb) {
    unsigned idx = blockIdx.x * blockDim.x + threadIdx.x;
    if (idx >= (unsigned)Tst * NBG * 8 * 2 * 32) return;
    int lane = idx & 31;
    unsigned r = idx >> 5;
    int c = r & 1; r >>= 1;
    int mt = r & 7; r >>= 3;
    int bg = r & 7;
    int t = r >> 3;
    unsigned oh[4];
#pragma unroll
    for (int reg = 0; reg < 4; ++reg) {
        int row = mt * 16 + (lane >> 2) + (reg & 1) * 8;
        int b = bg * 128 + row;
        int k = c * 16 + ((reg >> 1) & 1) * 8 + 2 * (lane & 3);
        oh[reg] = pack_h2(fetch_x(input, emb, t, b, k),
                          fetch_x(input, emb, t, b, k + 1));
    }
    unsigned* base = g_Xfrag + (size_t)(idx >> 5) * 128;
    *(uint4*)(base + lane * 4) = make_uint4(oh[0], oh[1], oh[2], oh[3]);
}

__global__ void prep_w_kernel(
    const float* __restrict__ Wih0, const float* __restrict__ Whh0,
    const float* __restrict__ bih0, const float* __restrict__ bhh0,
    const float* __restrict__ Wih1, const float* __restrict__ Whh1,
    const float* __restrict__ bih1, const float* __restrict__ bhh1) {
    const int NWF = NGS * NBLK * 512;
    int idx = blockIdx.x * blockDim.x + threadIdx.x;
    if (idx < NWF) {
        int hs = idx / (NBLK * 512);
        int rem = idx % (NBLK * 512);
        int blk = rem / 512, q = rem % 512;
        int ns = q >> 8, k2 = (q >> 7) & 1, L = (q >> 2) & 31, m = q & 3;
        int g = k2 * 2 + (m >> 1), regb = m & 1;
        int nt = g * 2 + ns;
        int mat, ch, hl;
        if (blk < 4) { mat = 0; hl = blk >> 1; ch = blk & 1; }
        else { int bb = blk - 4; mat = 1 + bb / 32; int cc = bb % 32; hl = cc >> 4; ch = cc & 15; }
        int k = ch * 16 + regb * 8 + 2 * (L & 3);
        int nl = nt * 8 + (L >> 2);
        int r = (nl >> 4) * 256 + hs * 16 + (nl & 15);
        float v0 = 0.f, v1 = 0.f;
        if (mat == 0) {
            if (k < 25)     v0 = Wih0[r * 25 + k];
            if (k + 1 < 25) v1 = Wih0[r * 25 + k + 1];
        } else if (mat == 1) { v0 = Whh0[r * 256 + k]; v1 = Whh0[r * 256 + k + 1]; }
        else if (mat == 2)   { v0 = Wih1[r * 256 + k]; v1 = Wih1[r * 256 + k + 1]; }
        else                 { v0 = Whh1[r * 256 + k]; v1 = Whh1[r * 256 + k + 1]; }
        unsigned hi, lo;
        splitw2(v0, v1, hi, lo);
        g_Wfrag[idx] = hl ? lo : hi;
    } else if (idx < NWF + 2048) {
        int i2 = idx - NWF;
        int l = i2 >> 10, rest = i2 & 1023, hs = rest >> 6, nl = rest & 63;
        int r = (nl >> 4) * 256 + hs * 16 + (nl & 15);
        g_biasP[i2] = (l == 0) ? (bih0[r] + bhh0[r]) : (bih1[r] + bhh1[r]);
    }
}

__global__ void init_h_kernel(const float* __restrict__ h0in) {
    unsigned idx = blockIdx.x * blockDim.x + threadIdx.x;
    if (idx < NBG) { g_cntA[idx] = 0; g_cntB[idx] = 0; }   // reset every replay
    if (idx >= 2u * NBG * 8 * 16 * 32) return;
    int lane = idx & 31;
    unsigned r = idx >> 5;
    int ch = r & 15; r >>= 4;
    int mt = r & 7; r >>= 3;
    int bg = r & 7;
    int l = r >> 3;
    unsigned oh[4];
#pragma unroll
    for (int reg = 0; reg < 4; ++reg) {
        int row = mt * 16 + (lane >> 2) + (reg & 1) * 8;
        int b = bg * 128 + row;
        int j = ch * 16 + ((reg >> 1) & 1) * 8 + 2 * (lane & 3);
        const float* src = h0in + (size_t)l * (Bsz * NH) + b * 256 + j;
        oh[reg] = pack_h2(src[0], src[1]);
    }
    unsigned* base = g_Hfrag + hoff(l, 0, bg, mt, ch);
    *(uint4*)(base + lane * 4) = make_uint4(oh[0], oh[1], oh[2], oh[3]);
}

// -------------------- monotonic split barrier --------------------
__device__ __forceinline__ void bar_arrive(unsigned* cnt, int grp) {
    __syncthreads();
    if (threadIdx.x == 0) {
        __threadfence();
        atomicAdd(&cnt[grp], 1u);
    }
}
__device__ __forceinline__ void bar_wait(unsigned* cnt, int grp, unsigned target) {
    if (threadIdx.x == 0) {
        volatile unsigned* gp = cnt + grp;
        while (*gp < target) { }
        __threadfence();
    }
    __syncthreads();
}

// -------------------- fragments --------------------
struct AF { unsigned h[4]; };
struct WF { unsigned b[16]; };   // Whi in [0,8), Wlo in [8,16)

__device__ __forceinline__ AF lda(const unsigned* __restrict__ A, int lane) {
    AF f;
    uint4 a = __ldcg((const uint4*)(A + lane * 4));
    f.h[0]=a.x; f.h[1]=a.y; f.h[2]=a.z; f.h[3]=a.w;
    return f;
}
__device__ __forceinline__ WF ldw(const uint4* __restrict__ smq, int blkh, int blkl,
                                  int lane, int ns) {
    WF w;
    const uint4* WH = smq + blkh * 128 + ns * 64;
    uint4 q0 = WH[lane], q1 = WH[32 + lane];
    const uint4* WL = smq + blkl * 128 + ns * 64;
    uint4 q2 = WL[lane], q3 = WL[32 + lane];
    w.b[0]=q0.x; w.b[1]=q0.y; w.b[2]=q0.z; w.b[3]=q0.w;
    w.b[4]=q1.x; w.b[5]=q1.y; w.b[6]=q1.z; w.b[7]=q1.w;
    w.b[8]=q2.x; w.b[9]=q2.y; w.b[10]=q2.z; w.b[11]=q2.w;
    w.b[12]=q3.x; w.b[13]=q3.y; w.b[14]=q3.z; w.b[15]=q3.w;
    return w;
}
__device__ __forceinline__ void mma_chunk(float (&acc)[4][4], const AF& a, const WF& w) {
#pragma unroll
    for (int g = 0; g < 4; ++g) mma4(acc[g], a.h, w.b[2*g], w.b[2*g+1]);
#pragma unroll
    for (int g = 0; g < 4; ++g) mma4(acc[g], a.h, w.b[8+2*g], w.b[8+2*g+1]);
}

// -------------------- epilogue --------------------
__device__ __forceinline__ void epilogue(int l, int pnew, int bg, int mt, int hs,
        int lane, int ns,
        float (&acc)[4][4], float (&cs)[2][2], const float* __restrict__ bias_s,
        float* __restrict__ outH) {
    int a = lane & 3;
    unsigned* base = g_Hfrag + hoff(l, pnew, bg, mt, hs);
    int lanep = (lane >> 2) * 4 + a;
#pragma unroll
    for (int rs = 0; rs < 2; ++rs) {
        float hv[2];
#pragma unroll
        for (int ui = 0; ui < 2; ++ui) {
            int u = ns * 8 + 2 * a + ui;
            int dr = rs * 2 + ui;
            float gi = acc[0][dr] + bias_s[l * 64 + u];
            float gf = acc[1][dr] + bias_s[l * 64 + 16 + u];
            float gg = acc[2][dr] + bias_s[l * 64 + 32 + u];
            float go = acc[3][dr] + bias_s[l * 64 + 48 + u];
            float c = fmaf(sigm(gf), cs[rs][ui], sigm(gi) * tanh_f(gg));
            cs[rs][ui] = c;
            hv[ui] = sigm(go) * tanh_f(c);
        }
        base[lanep * 4 + rs + 2 * ns] = pack_h2(hv[0], hv[1]);
        if (outH) {
            int b_row = bg * 128 + mt * 16 + (lane >> 2) + rs * 8;
#pragma unroll
            for (int ui = 0; ui < 2; ++ui)
                outH[(size_t)l * Bsz * NH + b_row * 256 + hs * 16 + ns * 8 + 2 * a + ui] = hv[ui];
        }
    }
}

// -------------------- main persistent kernel --------------------
// 128 CTAs x 512 threads. Warp (mt, ns): 16 rows x 32 gate cols.
// R15: depth-2 A prefetch in all phases + monotonic spin barrier.
__global__ void __launch_bounds__(512, 1) lstm_kernel(
    const float* __restrict__ h0in, const float* __restrict__ c0in,
    float* __restrict__ out) {
    extern __shared__ uint4 smq[];
    const int tid = threadIdx.x, lane = tid & 31, wid = tid >> 5;
    const int mt = wid & 7;
    const int ns = wid >> 3;
    const int bg = blockIdx.x >> 4;
    const int hs = blockIdx.x & 15;
    const int a = lane & 3;

    const uint4* wsrc = (const uint4*)g_Wfrag + (size_t)hs * (NBLK * 128);
    for (int i = tid; i < NBLK * 128; i += 512) smq[i] = wsrc[i];
    float* bias_s = (float*)(smq + NBLK * 128);
    if (tid < 128) bias_s[tid] = g_biasP[(tid >> 6) * 1024 + hs * 64 + (tid & 63)];
    __syncthreads();

    float cs0[2][2], cs1[2][2];
#pragma unroll
    for (int rs = 0; rs < 2; ++rs)
#pragma unroll
        for (int ui = 0; ui < 2; ++ui) {
            int u = ns * 8 + 2 * a + ui;
            int b_row = bg * 128 + mt * 16 + (lane >> 2) + rs * 8;
            int j = hs * 16 + u;
            cs0[rs][ui] = c0in[b_row * 256 + j];
            cs1[rs][ui] = c0in[Bsz * NH + b_row * 256 + j];
        }

    float* outH = out + 2 * Bsz;
    int p = 0;
    // cross-phase seeds (depth-2): X0, X1 of step 0
    AF sd0 = lda(g_Xfrag + xoff(0, bg, mt, 0), lane);
    AF sd1 = lda(g_Xfrag + xoff(0, bg, mt, 1), lane);

#pragma unroll 1
    for (int t = 0; t < Tst; ++t) {
        float acc[4][4];
#pragma unroll
        for (int g = 0; g < 4; ++g)
#pragma unroll
            for (int d = 0; d < 4; ++d) acc[g][d] = 0.f;

        // ================= L0: 18 chunks (X0, X1, H0..H15) =================
        {
            const unsigned* Hb = g_Hfrag + hoff(0, p, bg, mt, 0);
            AF aA = sd0, aB = sd1;
            WF w = ldw(smq, BLK_W0XH, BLK_W0XL, lane, ns);
#pragma unroll 1
            for (int i = 0; i < 18; ++i) {
                AF aN = aB;
                if (i + 2 < 18) aN = lda(Hb + (size_t)i * 128, lane);
                WF wN = w;
                if (i + 1 < 18) {
                    int nb = i + 1;
                    int bh = (nb < 2) ? BLK_W0XH + nb : BLK_W0HH + nb - 2;
                    int bl = (nb < 2) ? BLK_W0XL + nb : BLK_W0HL + nb - 2;
                    wN = ldw(smq, bh, bl, lane, ns);
                }
                mma_chunk(acc, aA, w);
                aA = aB; aB = aN; w = wN;
            }
        }
        // h1[p] (written step t-1) must be visible before L1A; waiting here
        // lets the L1A chunk 0/1 prefetch overlap the L0 epilogue.
        bar_wait(g_cntB, bg, (unsigned)(NGS * t));
        {
            const unsigned* Hb1 = g_Hfrag + hoff(1, p, bg, mt, 0);
            sd0 = lda(Hb1, lane);
            sd1 = lda(Hb1 + 128, lane);
        }

        epilogue(0, 1 - p, bg, mt, hs, lane, ns, acc, cs0, bias_s,
                 (t == Tst - 1) ? outH : nullptr);
        bar_arrive(g_cntA, bg);

#pragma unroll
        for (int g = 0; g < 4; ++g)
#pragma unroll
            for (int d = 0; d < 4; ++d) acc[g][d] = 0.f;

        // ================= L1 part A: W1h*h1[p], 16 chunks ==================
        {
            const unsigned* Hb = g_Hfrag + hoff(1, p, bg, mt, 0);
            AF aA = sd0, aB = sd1;
            WF w = ldw(smq, BLK_W1HH, BLK_W1HL, lane, ns);
#pragma unroll 1
            for (int c = 0; c < 16; ++c) {
                AF aN = aB;
                if (c + 2 < 16) aN = lda(Hb + (size_t)(c + 2) * 128, lane);
                WF wN = w;
                if (c + 1 < 16) wN = ldw(smq, BLK_W1HH + c + 1, BLK_W1HL + c + 1, lane, ns);
                mma_chunk(acc, aA, w);
                aA = aB; aB = aN; w = wN;
            }
        }
        // Prefetch L1B's own chunk (ch = hs): written by this CTA's L0
        // epilogue (covered by arrive's __syncthreads + fence) -> legal.
        {
            const unsigned* Hb = g_Hfrag + hoff(0, 1 - p, bg, mt, 0);
            sd0 = lda(Hb + (size_t)hs * 128, lane);
        }
        bar_wait(g_cntA, bg, (unsigned)(NGS * (t + 1)));

        // ================= L1 part B: W1x*h0[1-p], rotated from ch=hs =======
        {
            const unsigned* Hb = g_Hfrag + hoff(0, 1 - p, bg, mt, 0);
            AF aA = sd0;
            AF aB = lda(Hb + (size_t)((hs + 1) & 15) * 128, lane);
            WF w = ldw(smq, BLK_W1XH + hs, BLK_W1XL + hs, lane, ns);
#pragma unroll 1
            for (int i = 0; i < 16; ++i) {
                AF aN = aB;
                if (i + 2 < 16) aN = lda(Hb + (size_t)((hs + i + 2) & 15) * 128, lane);
                WF wN = w;
                if (i + 1 < 16) {
                    int ch2 = (hs + i + 1) & 15;
                    wN = ldw(smq, BLK_W1XH + ch2, BLK_W1XL + ch2, lane, ns);
                }
                mma_chunk(acc, aA, w);
                aA = aB; aB = aN; w = wN;
            }
        }
        // Prefetch next step's X0/X1 (static, safe).
        {
            int tt = (t + 1 < Tst) ? t + 1 : 0;
            sd0 = lda(g_Xfrag + xoff(tt, bg, mt, 0), lane);
            sd1 = lda(g_Xfrag + xoff(tt, bg, mt, 1), lane);
        }
        epilogue(1, 1 - p, bg, mt, hs, lane, ns, acc, cs1, bias_s,
                 (t == Tst - 1) ? outH : nullptr);
        bar_arrive(g_cntB, bg);
        p ^= 1;
    }

    float* outC = out + 2 * Bsz + 2 * Bsz * NH;
#pragma unroll
    for (int rs = 0; rs < 2; ++rs)
#pragma unroll
        for (int ui = 0; ui < 2; ++ui) {
            int u = ns * 8 + 2 * a + ui;
            int b_row = bg * 128 + mt * 16 + (lane >> 2) + rs * 8;
            int j = hs * 16 + u;
            outC[b_row * 256 + j] = cs0[rs][ui];
            outC[Bsz * NH + b_row * 256 + j] = cs1[rs][ui];
        }
}

// -------------------- decoded head --------------------
__global__ void decode_kernel(const float* __restrict__ fcw, const float* __restrict__ fcb,
                              const float* __restrict__ decw, const float* __restrict__ decb,
                              float* __restrict__ out) {
    int b = blockIdx.x * blockDim.x + threadIdx.x;
    if (b >= Bsz) return;
    const float* h1 = out + 2 * Bsz + Bsz * NH + b * 256;
    float d0 = decb[0], d1 = decb[1];
#pragma unroll 1
    for (int m = 0; m < 10; ++m) {
        float s = fcb[m];
        for (int j = 0; j < 256; ++j) s = fmaf(h1[j], fcw[m * 256 + j], s);
        s = fmaxf(s, 0.f);
        d0 = fmaf(s, decw[m], d0);
        d1 = fmaf(s, decw[10 + m], d1);
    }
    out[b] = d0;
    out[Bsz + b] = d1;
}

// -------------------- launch --------------------
extern "C" void kernel_launch(void* const* d_in, const int* in_sizes, int n_in,
                              void* d_out, int out_size) {
    const int*   input = (const int*)  d_in[0];
    const float* h0    = (const float*)d_in[1];
    const float* emb   = (const float*)d_in[3];
    const float* fcw   = (const float*)d_in[4];
    const float* fcb   = (const float*)d_in[5];
    const float* decw  = (const float*)d_in[6];
    const float* decb  = (const float*)d_in[7];
    float* out = (float*)d_out;

    cudaFuncSetAttribute(lstm_kernel, cudaFuncAttributeMaxDynamicSharedMemorySize, SMEM_SZ);

    unsigned nX = Tst * NBG * 8 * 2 * 32;
    pack_x_kernel<<<(nX + 255) / 256, 256>>>(input, emb);
    int nW = NGS * NBLK * 512 + 2048;
    prep_w_kernel<<<(nW + 255) / 256, 256>>>(
        (const float*)d_in[8], (const float*)d_in[9], (const float*)d_in[10], (const float*)d_in[11],
        (const float*)d_in[12], (const float*)d_in[13], (const float*)d_in[14], (const float*)d_in[15]);
    unsigned nH = 2 * NBG * 8 * 16 * 32;
    init_h_kernel<<<(nH + 255) / 256, 256>>>(h0);
    lstm_kernel<<<NCTA, 512, SMEM_SZ>>>(h0, (const float*)d_in[2], out);
    decode_kernel<<<(Bsz + 255) / 256, 256>>>(fcw, fcb, decw, decb, out);
}

// round 16
// speedup vs baseline: 1.2955x; 1.2955x over previous
#include <cuda_runtime.h>
#include <cuda_fp16.h>

#define Bsz 1024
#define Tst 300
#define NH  256
#define NBG 8      // batch groups (128 rows)
#define NGS 16     // gate-slice CTAs per group (64 gate cols each)
#define NCTA 128

#define BLK_W0XH 0
#define BLK_W0XL 2
#define BLK_W0HH 4
#define BLK_W0HL 20
#define BLK_W1XH 36
#define BLK_W1XL 52
#define BLK_W1HH 68
#define BLK_W1HL 84
#define NBLK     100
#define SMEM_SZ  (NBLK * 2048 + 512)

// -------------------- device scratch --------------------
__device__ unsigned g_Wfrag[(size_t)NGS * NBLK * 512];        // fp16 hi/lo W fragments
__device__ float    g_biasP[2 * NGS * 64];
__device__ unsigned g_Xfrag[(size_t)Tst * NBG * 8 * 2 * 128]; // fp16 A fragments (20 MB)
__device__ unsigned g_Hfrag[2 * 2 * NBG * 8 * 16 * 128];      // fp16 h fragments (2 MB)
__device__ unsigned g_cntA[NBG], g_genA[NBG];
__device__ unsigned g_cntB[NBG], g_genB[NBG];

__device__ __forceinline__ size_t hoff(int l, int buf, int bg, int mt, int ch) {
    return ((((((size_t)(l * 2 + buf)) * NBG + bg) * 8 + mt) * 16 + ch) * 128);
}
__device__ __forceinline__ size_t xoff(int t, int bg, int mt, int c) {
    return ((((size_t)t * NBG + bg) * 8 + mt) * 2 + c) * 128;
}

__device__ __forceinline__ unsigned pack_h2(float v0, float v1) {
    __half2 h = __floats2half2_rn(v0, v1);
    return *(unsigned*)&h;
}
__device__ __forceinline__ void splitw2(float v0, float v1, unsigned& hi, unsigned& lo) {
    __half h0 = __float2half_rn(v0), h1 = __float2half_rn(v1);
    __half l0 = __float2half_rn(v0 - __half2float(h0));
    __half l1 = __float2half_rn(v1 - __half2float(h1));
    hi = (unsigned)*(unsigned short*)&h0 | ((unsigned)*(unsigned short*)&h1 << 16);
    lo = (unsigned)*(unsigned short*)&l0 | ((unsigned)*(unsigned short*)&l1 << 16);
}
__device__ __forceinline__ float sigm(float x) { return 1.f / (1.f + __expf(-x)); }
__device__ __forceinline__ float tanh_f(float x) {
    x = fminf(fmaxf(x, -15.f), 15.f);
    float e = __expf(2.f * x);
    return __fdividef(e - 1.f, e + 1.f);
}

__device__ __forceinline__ void mma4(float* d, const unsigned* a, unsigned b0, unsigned b1) {
    asm volatile("mma.sync.aligned.m16n8k16.row.col.f32.f16.f16.f32 "
        "{%0,%1,%2,%3}, {%4,%5,%6,%7}, {%8,%9}, {%0,%1,%2,%3};"
        : "+f"(d[0]), "+f"(d[1]), "+f"(d[2]), "+f"(d[3])
        : "r"(a[0]), "r"(a[1]), "r"(a[2]), "r"(a[3]), "r"(b0), "r"(b1));
}

// -------------------- x gather --------------------
__device__ __forceinline__ float fetch_x(const int* __restrict__ input,
                                         const float* __restrict__ emb,
                                         int t, int b, int k) {
    if (k >= 25) return 0.f;
    long flat = (long)t * (Bsz * 25) + b * 25 + k;
    int s = (int)(flat / (Bsz * 300));
    int rr = (int)(flat % (Bsz * 300));
    int bb = rr / 300, e = rr % 300;
    return emb[(long)input[bb * 25 + s] * 300 + e];
}

// -------------------- prep kernels --------------------
__global__ void pack_x_kernel(const int* __restrict__ input, const float* __restrict__ emb) {
    unsigned idx = blockIdx.x * blockDim.x + threadIdx.x;
    if (idx >= (unsigned)Tst * NBG * 8 * 2 * 32) return;
    int lane = idx & 31;
    unsigned r = idx >> 5;
    int c = r & 1; r >>= 1;
    int mt = r & 7; r >>= 3;
    int bg = r & 7;
    int t = r >> 3;
    unsigned oh[4];
#pragma unroll
    for (int reg = 0; reg < 4; ++reg) {
        int row = mt * 16 + (lane >> 2) + (reg & 1) * 8;
        int b = bg * 128 + row;
        int k = c * 16 + ((reg >> 1) & 1) * 8 + 2 * (lane & 3);
        oh[reg] = pack_h2(fetch_x(input, emb, t, b, k),
                          fetch_x(input, emb, t, b, k + 1));
    }
    unsigned* base = g_Xfrag + (size_t)(idx >> 5) * 128;
    *(uint4*)(base + lane * 4) = make_uint4(oh[0], oh[1], oh[2], oh[3]);
}

__global__ void prep_w_kernel(
    const float* __restrict__ Wih0, const float* __restrict__ Whh0,
    const float* __restrict__ bih0, const float* __restrict__ bhh0,
    const float* __restrict__ Wih1, const float* __restrict__ Whh1,
    const float* __restrict__ bih1, const float* __restrict__ bhh1) {
    const int NWF = NGS * NBLK * 512;
    int idx = blockIdx.x * blockDim.x + threadIdx.x;
    if (idx < NWF) {
        int hs = idx / (NBLK * 512);
        int rem = idx % (NBLK * 512);
        int blk = rem / 512, q = rem % 512;
        int ns = q >> 8, k2 = (q >> 7) & 1, L = (q >> 2) & 31, m = q & 3;
        int g = k2 * 2 + (m >> 1), regb = m & 1;
        int nt = g * 2 + ns;
        int mat, ch, hl;
        if (blk < 4) { mat = 0; hl = blk >> 1; ch = blk & 1; }
        else { int bb = blk - 4; mat = 1 + bb / 32; int cc = bb % 32; hl = cc >> 4; ch = cc & 15; }
        int k = ch * 16 + regb * 8 + 2 * (L & 3);
        int nl = nt * 8 + (L >> 2);
        int r = (nl >> 4) * 256 + hs * 16 + (nl & 15);
        float v0 = 0.f, v1 = 0.f;
        if (mat == 0) {
            if (k < 25)     v0 = Wih0[r * 25 + k];
            if (k + 1 < 25) v1 = Wih0[r * 25 + k + 1];
        } else if (mat == 1) { v0 = Whh0[r * 256 + k]; v1 = Whh0[r * 256 + k + 1]; }
        else if (mat == 2)   { v0 = Wih1[r * 256 + k]; v1 = Wih1[r * 256 + k + 1]; }
        else                 { v0 = Whh1[r * 256 + k]; v1 = Whh1[r * 256 + k + 1]; }
        unsigned hi, lo;
        splitw2(v0, v1, hi, lo);
        g_Wfrag[idx] = hl ? lo : hi;
    } else if (idx < NWF + 2048) {
        int i2 = idx - NWF;
        int l = i2 >> 10, rest = i2 & 1023, hs = rest >> 6, nl = rest & 63;
        int r = (nl >> 4) * 256 + hs * 16 + (nl & 15);
        g_biasP[i2] = (l == 0) ? (bih0[r] + bhh0[r]) : (bih1[r] + bhh1[r]);
    }
}

__global__ void init_h_kernel(const float* __restrict__ h0in) {
    unsigned idx = blockIdx.x * blockDim.x + threadIdx.x;
    if (idx < NBG) {
        g_cntA[idx] = 0; g_genA[idx] = 0;
        g_cntB[idx] = 0; g_genB[idx] = 0;
    }
    if (idx >= 2u * NBG * 8 * 16 * 32) return;
    int lane = idx & 31;
    unsigned r = idx >> 5;
    int ch = r & 15; r >>= 4;
    int mt = r & 7; r >>= 3;
    int bg = r & 7;
    int l = r >> 3;
    unsigned oh[4];
#pragma unroll
    for (int reg = 0; reg < 4; ++reg) {
        int row = mt * 16 + (lane >> 2) + (reg & 1) * 8;
        int b = bg * 128 + row;
        int j = ch * 16 + ((reg >> 1) & 1) * 8 + 2 * (lane & 3);
        const float* src = h0in + (size_t)l * (Bsz * NH) + b * 256 + j;
        oh[reg] = pack_h2(src[0], src[1]);
    }
    unsigned* base = g_Hfrag + hoff(l, 0, bg, mt, ch);
    *(uint4*)(base + lane * 4) = make_uint4(oh[0], oh[1], oh[2], oh[3]);
}

// -------------------- split group barrier (R14-proven) --------------------
__device__ __forceinline__ void bar_arrive(unsigned* cnt, unsigned* gen, int grp) {
    __syncthreads();
    if (threadIdx.x == 0) {
        __threadfence();
        unsigned old = atomicAdd(&cnt[grp], 1u);
        if (old == NGS - 1) {
            atomicExch(&cnt[grp], 0u);
            __threadfence();
            atomicAdd(&gen[grp], 1u);
        }
    }
}
__device__ __forceinline__ void bar_wait(unsigned* gen, int grp, unsigned target) {
    if (threadIdx.x == 0) {
        volatile unsigned* gp = gen + grp;
        while (*gp < target) __nanosleep(32);
        __threadfence();
    }
    __syncthreads();
}

// -------------------- fragments --------------------
struct AF { unsigned h[4]; };
struct WF { unsigned b[16]; };   // Whi in [0,8), Wlo in [8,16)

__device__ __forceinline__ AF lda(const unsigned* __restrict__ A, int lane) {
    AF f;
    uint4 a = __ldcg((const uint4*)(A + lane * 4));
    f.h[0]=a.x; f.h[1]=a.y; f.h[2]=a.z; f.h[3]=a.w;
    return f;
}
__device__ __forceinline__ WF ldw(const uint4* __restrict__ smq, int blkh, int blkl,
                                  int lane, int ns) {
    WF w;
    const uint4* WH = smq + blkh * 128 + ns * 64;
    uint4 q0 = WH[lane], q1 = WH[32 + lane];
    const uint4* WL = smq + blkl * 128 + ns * 64;
    uint4 q2 = WL[lane], q3 = WL[32 + lane];
    w.b[0]=q0.x; w.b[1]=q0.y; w.b[2]=q0.z; w.b[3]=q0.w;
    w.b[4]=q1.x; w.b[5]=q1.y; w.b[6]=q1.z; w.b[7]=q1.w;
    w.b[8]=q2.x; w.b[9]=q2.y; w.b[10]=q2.z; w.b[11]=q2.w;
    w.b[12]=q3.x; w.b[13]=q3.y; w.b[14]=q3.z; w.b[15]=q3.w;
    return w;
}
__device__ __forceinline__ void mma_chunk(float (&acc)[4][4], const AF& a, const WF& w) {
#pragma unroll
    for (int g = 0; g < 4; ++g) mma4(acc[g], a.h, w.b[2*g], w.b[2*g+1]);
#pragma unroll
    for (int g = 0; g < 4; ++g) mma4(acc[g], a.h, w.b[8+2*g], w.b[8+2*g+1]);
}

// -------------------- epilogue --------------------
__device__ __forceinline__ void epilogue(int l, int pnew, int bg, int mt, int hs,
        int lane, int ns,
        float (&acc)[4][4], float (&cs)[2][2], const float* __restrict__ bias_s,
        float* __restrict__ outH) {
    int a = lane & 3;
    unsigned* base = g_Hfrag + hoff(l, pnew, bg, mt, hs);
    int lanep = (lane >> 2) * 4 + a;
#pragma unroll
    for (int rs = 0; rs < 2; ++rs) {
        float hv[2];
#pragma unroll
        for (int ui = 0; ui < 2; ++ui) {
            int u = ns * 8 + 2 * a + ui;
            int dr = rs * 2 + ui;
            float gi = acc[0][dr] + bias_s[l * 64 + u];
            float gf = acc[1][dr] + bias_s[l * 64 + 16 + u];
            float gg = acc[2][dr] + bias_s[l * 64 + 32 + u];
            float go = acc[3][dr] + bias_s[l * 64 + 48 + u];
            float c = fmaf(sigm(gf), cs[rs][ui], sigm(gi) * tanh_f(gg));
            cs[rs][ui] = c;
            hv[ui] = sigm(go) * tanh_f(c);
        }
        base[lanep * 4 + rs + 2 * ns] = pack_h2(hv[0], hv[1]);
        if (outH) {
            int b_row = bg * 128 + mt * 16 + (lane >> 2) + rs * 8;
#pragma unroll
            for (int ui = 0; ui < 2; ++ui)
                outH[(size_t)l * Bsz * NH + b_row * 256 + hs * 16 + ns * 8 + 2 * a + ui] = hv[ui];
        }
    }
}

// -------------------- main persistent kernel --------------------
// 128 CTAs x 512 threads. Warp (mt, ns): 16 rows x 32 gate cols.
// R16 = R14 (best) with the three chunk loops FULLY UNROLLED so all SMEM
// block offsets / global chunk offsets are compile-time immediates.
__global__ void __launch_bounds__(512, 1) lstm_kernel(
    const float* __restrict__ h0in, const float* __restrict__ c0in,
    float* __restrict__ out) {
    extern __shared__ uint4 smq[];
    const int tid = threadIdx.x, lane = tid & 31, wid = tid >> 5;
    const int mt = wid & 7;
    const int ns = wid >> 3;
    const int bg = blockIdx.x >> 4;
    const int hs = blockIdx.x & 15;
    const int a = lane & 3;

    const uint4* wsrc = (const uint4*)g_Wfrag + (size_t)hs * (NBLK * 128);
    for (int i = tid; i < NBLK * 128; i += 512) smq[i] = wsrc[i];
    float* bias_s = (float*)(smq + NBLK * 128);
    if (tid < 128) bias_s[tid] = g_biasP[(tid >> 6) * 1024 + hs * 64 + (tid & 63)];
    __syncthreads();

    float cs0[2][2], cs1[2][2];
#pragma unroll
    for (int rs = 0; rs < 2; ++rs)
#pragma unroll
        for (int ui = 0; ui < 2; ++ui) {
            int u = ns * 8 + 2 * a + ui;
            int b_row = bg * 128 + mt * 16 + (lane >> 2) + rs * 8;
            int j = hs * 16 + u;
            cs0[rs][ui] = c0in[b_row * 256 + j];
            cs1[rs][ui] = c0in[Bsz * NH + b_row * 256 + j];
        }

    float* outH = out + 2 * Bsz;
    int p = 0;
    AF a_seed = lda(g_Xfrag + xoff(0, bg, mt, 0), lane);

#pragma unroll 1
    for (int t = 0; t < Tst; ++t) {
        float acc[4][4];
#pragma unroll
        for (int g = 0; g < 4; ++g)
#pragma unroll
            for (int d = 0; d < 4; ++d) acc[g][d] = 0.f;

        // ================= L0: x(2 chunks) + W0h*h0[p](16 chunks) ==========
        {
            const unsigned* Hb = g_Hfrag + hoff(0, p, bg, mt, 0);
            AF a_cur = a_seed;
            WF w_cur = ldw(smq, BLK_W0XH + 0, BLK_W0XL + 0, lane, ns);
            AF a_nxt = lda(g_Xfrag + xoff(t, bg, mt, 1), lane);
            WF w_nxt = ldw(smq, BLK_W0XH + 1, BLK_W0XL + 1, lane, ns);
            mma_chunk(acc, a_cur, w_cur);
            a_cur = a_nxt; w_cur = w_nxt;
            a_nxt = lda(Hb, lane);
            w_nxt = ldw(smq, BLK_W0HH + 0, BLK_W0HL + 0, lane, ns);
            mma_chunk(acc, a_cur, w_cur);
#pragma unroll
            for (int c = 0; c < 16; ++c) {
                a_cur = a_nxt; w_cur = w_nxt;
                if (c < 15) {
                    a_nxt = lda(Hb + (size_t)(c + 1) * 128, lane);
                    w_nxt = ldw(smq, BLK_W0HH + c + 1, BLK_W0HL + c + 1, lane, ns);
                }
                mma_chunk(acc, a_cur, w_cur);
            }
        }
        bar_wait(g_genB, bg, (unsigned)t);
        a_seed = lda(g_Hfrag + hoff(1, p, bg, mt, 0), lane);

        epilogue(0, 1 - p, bg, mt, hs, lane, ns, acc, cs0, bias_s,
                 (t == Tst - 1) ? outH : nullptr);
        bar_arrive(g_cntA, g_genA, bg);

#pragma unroll
        for (int g = 0; g < 4; ++g)
#pragma unroll
            for (int d = 0; d < 4; ++d) acc[g][d] = 0.f;

        // ================= L1 part A: W1h*h1[p], 16 chunks ==================
        {
            const unsigned* Hb = g_Hfrag + hoff(1, p, bg, mt, 0);
            AF a_cur = a_seed;
            WF w_cur = ldw(smq, BLK_W1HH + 0, BLK_W1HL + 0, lane, ns);
            AF a_nxt = a_cur; WF w_nxt = w_cur;
#pragma unroll
            for (int c = 0; c < 16; ++c) {
                if (c < 15) {
                    a_nxt = lda(Hb + (size_t)(c + 1) * 128, lane);
                    w_nxt = ldw(smq, BLK_W1HH + c + 1, BLK_W1HL + c + 1, lane, ns);
                }
                mma_chunk(acc, a_cur, w_cur);
                a_cur = a_nxt; w_cur = w_nxt;
            }
        }
        a_seed = lda(g_Hfrag + hoff(0, 1 - p, bg, mt, hs), lane);   // own chunk, legal pre-wait
        bar_wait(g_genA, bg, (unsigned)(t + 1));

        // ================= L1 part B: W1x*h0[1-p], rotated from ch=hs =======
        {
            const unsigned* Hb = g_Hfrag + hoff(0, 1 - p, bg, mt, 0);
            AF a_cur = a_seed;
            WF w_cur = ldw(smq, BLK_W1XH + hs, BLK_W1XL + hs, lane, ns);
            AF a_nxt = a_cur; WF w_nxt = w_cur;
#pragma unroll
            for (int i = 0; i < 16; ++i) {
                if (i < 15) {
                    int ch2 = (hs + i + 1) & 15;
                    a_nxt = lda(Hb + (size_t)ch2 * 128, lane);
                    w_nxt = ldw(smq, BLK_W1XH + ch2, BLK_W1XL + ch2, lane, ns);
                }
                mma_chunk(acc, a_cur, w_cur);
                a_cur = a_nxt; w_cur = w_nxt;
            }
        }
        {
            int tt = (t + 1 < Tst) ? t + 1 : 0;
            a_seed = lda(g_Xfrag + xoff(tt, bg, mt, 0), lane);
        }
        epilogue(1, 1 - p, bg, mt, hs, lane, ns, acc, cs1, bias_s,
                 (t == Tst - 1) ? outH : nullptr);
        bar_arrive(g_cntB, g_genB, bg);
        p ^= 1;
    }

    float* outC = out + 2 * Bsz + 2 * Bsz * NH;
#pragma unroll
    for (int rs = 0; rs < 2; ++rs)
#pragma unroll
        for (int ui = 0; ui < 2; ++ui) {
            int u = ns * 8 + 2 * a + ui;
            int b_row = bg * 128 + mt * 16 + (lane >> 2) + rs * 8;
            int j = hs * 16 + u;
            outC[b_row * 256 + j] = cs0[rs][ui];
            outC[Bsz * NH + b_row * 256 + j] = cs1[rs][ui];
        }
}

// -------------------- decoded head --------------------
__global__ void decode_kernel(const float* __restrict__ fcw, const float* __restrict__ fcb,
                              const float* __restrict__ decw, const float* __restrict__ decb,
                              float* __restrict__ out) {
    int b = blockIdx.x * blockDim.x + threadIdx.x;
    if (b >= Bsz) return;
    const float* h1 = out + 2 * Bsz + Bsz * NH + b * 256;
    float d0 = decb[0], d1 = decb[1];
#pragma unroll 1
    for (int m = 0; m < 10; ++m) {
        float s = fcb[m];
        for (int j = 0; j < 256; ++j) s = fmaf(h1[j], fcw[m * 256 + j], s);
        s = fmaxf(s, 0.f);
        d0 = fmaf(s, decw[m], d0);
        d1 = fmaf(s, decw[10 + m], d1);
    }
    out[b] = d0;
    out[Bsz + b] = d1;
}

// -------------------- launch --------------------
extern "C" void kernel_launch(void* const* d_in, const int* in_sizes, int n_in,
                              void* d_out, int out_size) {
    const int*   input = (const int*)  d_in[0];
    const float* h0    = (const float*)d_in[1];
    const float* emb   = (const float*)d_in[3];
    const float* fcw   = (const float*)d_in[4];
    const float* fcb   = (const float*)d_in[5];
    const float* decw  = (const float*)d_in[6];
    const float* decb  = (const float*)d_in[7];
    float* out = (float*)d_out;

    cudaFuncSetAttribute(lstm_kernel, cudaFuncAttributeMaxDynamicSharedMemorySize, SMEM_SZ);

    unsigned nX = Tst * NBG * 8 * 2 * 32;
    pack_x_kernel<<<(nX + 255) / 256, 256>>>(input, emb);
    int nW = NGS * NBLK * 512 + 2048;
    prep_w_kernel<<<(nW + 255) / 256, 256>>>(
        (const float*)d_in[8], (const float*)d_in[9], (const float*)d_in[10], (const float*)d_in[11],
        (const float*)d_in[12], (const float*)d_in[13], (const float*)d_in[14], (const float*)d_in[15]);
    unsigned nH = 2 * NBG * 8 * 16 * 32;
    init_h_kernel<<<(nH + 255) / 256, 256>>>(h0);
    lstm_kernel<<<NCTA, 512, SMEM_SZ>>>(h0, (const float*)d_in[2], out);
    decode_kernel<<<(Bsz + 255) / 256, 256>>>(fcw, fcb, decw, decb, out);
}